// round 7
// baseline (speedup 1.0000x reference)
#include <cuda_runtime.h>
#include <cuda_bf16.h>
#include <cstdint>

// Packed-varlen (SEG=1024) causal attention + additive bias, fp32 I/O.
// Round 7: round-6 structure + (a) accumulator-interleaved mma ordering in QK
// and PV (RAW distance 8 / 4), (b) bias tile prefetched via cp.async into
// double-buffered smem (272B stride, conflict-free), read by softmax from LDS.

#define SQ   2048
#define NB   2
#define NHD  16
#define HD   128
#define SEG  1024
#define BM   128
#define BN   64
#define NT   256
#define ROWSTRIDE (NB*NHD*HD)
#define ATTN_SCALE 0.08838834764831845f

// scratch: per (b,h,s) one 512B row = [hi 128 bf16 | lo 128 bf16]
__device__ __align__(256) static unsigned char KHL[(size_t)NB * NHD * SQ * 512];
__device__ __align__(256) static unsigned char VHL[(size_t)NB * NHD * SQ * 512];

// smem: K dbuf, V dbuf (Q staging aliases V), bias dbuf. All 34816B buffers.
#define TSTR 272
#define TILE_H 17408
#define BUF_SZ 34816
#define SM_K 0
#define SM_V 69632
#define SM_QSTG 69632              // prologue only (aliases both V buffers)
#define SM_B 139264                // bias: 128 rows x 272B per buffer
#define SMEM_TOTAL 208896

__device__ __forceinline__ uint32_t s2u(const void* p) {
    uint32_t a;
    asm("{ .reg .u64 t; cvta.to.shared.u64 t, %1; cvt.u32.u64 %0, t; }" : "=r"(a) : "l"(p));
    return a;
}
__device__ __forceinline__ void split2(float a, float b, uint32_t& hi, uint32_t& lo) {
    __nv_bfloat16 ah = __float2bfloat16_rn(a);
    __nv_bfloat16 bh = __float2bfloat16_rn(b);
    __nv_bfloat16 al = __float2bfloat16_rn(a - __bfloat162float(ah));
    __nv_bfloat16 bl = __float2bfloat16_rn(b - __bfloat162float(bh));
    hi = ((uint32_t)__bfloat16_as_ushort(bh) << 16) | __bfloat16_as_ushort(ah);
    lo = ((uint32_t)__bfloat16_as_ushort(bl) << 16) | __bfloat16_as_ushort(al);
}
__device__ __forceinline__ void ldsm4(uint32_t* r, uint32_t a) {
    asm volatile("ldmatrix.sync.aligned.m8n8.x4.shared.b16 {%0,%1,%2,%3}, [%4];"
                 : "=r"(r[0]), "=r"(r[1]), "=r"(r[2]), "=r"(r[3]) : "r"(a));
}
__device__ __forceinline__ void ldsm4t(uint32_t* r, uint32_t a) {
    asm volatile("ldmatrix.sync.aligned.m8n8.x4.trans.shared.b16 {%0,%1,%2,%3}, [%4];"
                 : "=r"(r[0]), "=r"(r[1]), "=r"(r[2]), "=r"(r[3]) : "r"(a));
}
__device__ __forceinline__ void mma16816(float* c, const uint32_t* a, const uint32_t* b) {
    asm volatile("mma.sync.aligned.m16n8k16.row.col.f32.bf16.bf16.f32 "
                 "{%0,%1,%2,%3}, {%4,%5,%6,%7}, {%8,%9}, {%0,%1,%2,%3};"
                 : "+f"(c[0]), "+f"(c[1]), "+f"(c[2]), "+f"(c[3])
                 : "r"(a[0]), "r"(a[1]), "r"(a[2]), "r"(a[3]), "r"(b[0]), "r"(b[1]));
}
#define CPASYNC16(s, g) asm volatile("cp.async.cg.shared.global [%0], [%1], 16;" :: "r"(s), "l"(g))
#define CPCOMMIT()      asm volatile("cp.async.commit_group;" ::: "memory")
#define CPWAIT0()       asm volatile("cp.async.wait_group 0;" ::: "memory")

// ---- pre-pass: K,V fp32 -> bf16 hi/lo rows in scratch ----
__global__ __launch_bounds__(256)
void convert_kv(const float* __restrict__ Kg, const float* __restrict__ Vg) {
    const int idx = blockIdx.x * 256 + threadIdx.x;
    const int row = idx >> 5, f4 = idx & 31;
    const int bh = row >> 11, s = row & 2047;
    const size_t src = (size_t)s * ROWSTRIDE + bh * HD + f4 * 4;
    const size_t dst = (size_t)row * 512 + f4 * 8;
    float4 k = *(const float4*)(Kg + src);
    float4 v = *(const float4*)(Vg + src);
    uint32_t h0, l0, h1, l1;
    split2(k.x, k.y, h0, l0); split2(k.z, k.w, h1, l1);
    *(uint2*)(KHL + dst)       = make_uint2(h0, h1);
    *(uint2*)(KHL + dst + 256) = make_uint2(l0, l1);
    split2(v.x, v.y, h0, l0); split2(v.z, v.w, h1, l1);
    *(uint2*)(VHL + dst)       = make_uint2(h0, h1);
    *(uint2*)(VHL + dst + 256) = make_uint2(l0, l1);
}

// cp.async one 64-row K/V tile (hi+lo) from scratch into smem buffer.
__device__ __forceinline__ void issue_tile(const unsigned char* scratch, uint32_t sb,
                                           uint32_t smbase, int bh, int g0, int tid) {
#pragma unroll
    for (int i = 0; i < 8; i++) {
        const int c = tid + NT * i, row = c >> 5, f4 = c & 31;
        const unsigned char* src = scratch + (((size_t)(bh * SQ + g0 + row)) << 9) + f4 * 16;
        const uint32_t dst = (f4 < 16) ? (sb + smbase + row * TSTR + f4 * 16)
                                       : (sb + smbase + TILE_H + row * TSTR + (f4 - 16) * 16);
        CPASYNC16(dst, src);
    }
}
// cp.async one 128x64 fp32 bias tile (rows q0.., cols k0..k0+63).
__device__ __forceinline__ void issue_bias(const float* Bp, uint32_t sb, uint32_t smbase,
                                           int q0, int k0, int tid) {
#pragma unroll
    for (int i = 0; i < 8; i++) {
        const int c = tid + NT * i, row = c >> 4, f4 = c & 15;
        CPASYNC16(sb + smbase + row * TSTR + f4 * 16,
                  Bp + (size_t)(q0 + row) * SQ + k0 + f4 * 4);
    }
}

__global__ __launch_bounds__(NT, 1)
void attn_hmma(const float* __restrict__ Qg, const float* __restrict__ Bias,
               float* __restrict__ Out) {
    extern __shared__ char smem[];
    const uint32_t sb = s2u(smem);
    const int tid = threadIdx.x, lane = tid & 31, warp = tid >> 5;
    const int m0 = warp * 16;
    const int tile = 15 - (int)blockIdx.x;
    const int head = blockIdx.y, batch = blockIdx.z;
    const int q0 = tile * BM, seg0 = (q0 / SEG) * SEG;
    const int bh = batch * NHD + head;
    const int base = bh * HD;
    const int nkt = (q0 - seg0) / BN + 2;
    const float* Bp = Bias + (size_t)batch * SQ * SQ;

    // ---- prologue: K0 + bias0 cp.async; Q -> staging -> persistent frags ----
    issue_tile(KHL, sb, SM_K, bh, seg0, tid);
    issue_bias(Bp, sb, SM_B, q0, seg0, tid);
    CPCOMMIT();
#pragma unroll
    for (int i = 0; i < 16; i++) {
        const int idx = tid + NT * i, row = idx >> 5, f4 = idx & 31;
        const float4 v = *(const float4*)(Qg + (size_t)(q0 + row) * ROWSTRIDE + base + f4 * 4);
        uint32_t h0, l0, h1, l1;
        split2(v.x, v.y, h0, l0); split2(v.z, v.w, h1, l1);
        *(uint2*)(smem + SM_QSTG + row * TSTR + f4 * 8)          = make_uint2(h0, h1);
        *(uint2*)(smem + SM_QSTG + BUF_SZ + row * TSTR + f4 * 8) = make_uint2(l0, l1);
    }
    __syncthreads();
    uint32_t qH[8][4], qL[8][4];
#pragma unroll
    for (int ks = 0; ks < 8; ks++) {
        const uint32_t ad = sb + SM_QSTG + (m0 + (lane & 15)) * TSTR
                          + ks * 32 + (lane >> 4) * 16;
        ldsm4(qH[ks], ad);
        ldsm4(qL[ks], ad + BUF_SZ);
    }
    __syncthreads();                          // staging free -> V buffers
    issue_tile(VHL, sb, SM_V, bh, seg0, tid);
    CPCOMMIT();

    float o[16][4];
#pragma unroll
    for (int j = 0; j < 16; j++)
#pragma unroll
        for (int r = 0; r < 4; r++) o[j][r] = 0.f;
    float lsum0 = 0.f, lsum1 = 0.f;

    const int r0 = lane >> 2, q2 = (lane & 3) * 2;
    const int qr0 = q0 + m0 + r0, qr1 = qr0 + 8;

    for (int kt = 0; kt < nkt; kt++) {
        const int k0 = seg0 + kt * BN;
        const uint32_t kb = SM_K + (kt & 1) * BUF_SZ;
        const uint32_t vb = SM_V + (kt & 1) * BUF_SZ;
        const char* bB = smem + SM_B + (kt & 1) * BUF_SZ;
        CPWAIT0();
        __syncthreads();

        if (kt + 1 < nkt) {
            const uint32_t nb = (kt + 1) & 1;
            issue_tile(KHL, sb, SM_K + nb * BUF_SZ, bh, k0 + BN, tid);
            issue_tile(VHL, sb, SM_V + nb * BUF_SZ, bh, k0 + BN, tid);
            issue_bias(Bp, sb, SM_B + nb * BUF_SZ, q0, k0 + BN, tid);
            CPCOMMIT();
        }

        // ---- S = Q K^T : 3 phases x 8 independent accumulators ----
        float c[8][4];
#pragma unroll
        for (int f = 0; f < 8; f++)
#pragma unroll
            for (int r = 0; r < 4; r++) c[f][r] = 0.f;

#pragma unroll
        for (int ks = 0; ks < 8; ks++) {
            uint32_t bH[4][4], bL[4][4];
#pragma unroll
            for (int g = 0; g < 4; g++) {
                const uint32_t bd = sb + kb + (g * 16 + ((lane >> 4) & 1) * 8 + (lane & 7)) * TSTR
                                  + ks * 32 + ((lane >> 3) & 1) * 16;
                ldsm4(bH[g], bd);
                ldsm4(bL[g], bd + TILE_H);
            }
#pragma unroll
            for (int g = 0; g < 4; g++) {
                mma16816(c[2 * g],     qH[ks], &bH[g][0]);
                mma16816(c[2 * g + 1], qH[ks], &bH[g][2]);
            }
#pragma unroll
            for (int g = 0; g < 4; g++) {
                mma16816(c[2 * g],     qH[ks], &bL[g][0]);
                mma16816(c[2 * g + 1], qH[ks], &bL[g][2]);
            }
#pragma unroll
            for (int g = 0; g < 4; g++) {
                mma16816(c[2 * g],     qL[ks], &bH[g][0]);
                mma16816(c[2 * g + 1], qL[ks], &bH[g][2]);
            }
        }

        // ---- softmax (no max-sub; scores O(6)) + causal + bias from LDS ----
#pragma unroll
        for (int f = 0; f < 8; f++) {
            const int col = k0 + f * 8 + q2;
            const int boff = (f * 8 + q2) * 4;
            const float2 b0 = *(const float2*)(bB + (m0 + r0) * TSTR + boff);
            const float2 b1 = *(const float2*)(bB + (m0 + r0 + 8) * TSTR + boff);
            const float p0 = (col     <= qr0) ? __expf(c[f][0] * ATTN_SCALE + b0.x) : 0.f;
            const float p1 = (col + 1 <= qr0) ? __expf(c[f][1] * ATTN_SCALE + b0.y) : 0.f;
            const float p2 = (col     <= qr1) ? __expf(c[f][2] * ATTN_SCALE + b1.x) : 0.f;
            const float p3 = (col + 1 <= qr1) ? __expf(c[f][3] * ATTN_SCALE + b1.y) : 0.f;
            lsum0 += p0 + p1;
            lsum1 += p2 + p3;
            c[f][0] = p0; c[f][1] = p1; c[f][2] = p2; c[f][3] = p3;
        }
        uint32_t pH[4][4], pL[4][4];
#pragma unroll
        for (int t = 0; t < 4; t++) {
            split2(c[2 * t][0],     c[2 * t][1],     pH[t][0], pL[t][0]);
            split2(c[2 * t][2],     c[2 * t][3],     pH[t][1], pL[t][1]);
            split2(c[2 * t + 1][0], c[2 * t + 1][1], pH[t][2], pL[t][2]);
            split2(c[2 * t + 1][2], c[2 * t + 1][3], pH[t][3], pL[t][3]);
        }

        // ---- O += P V : V columns in pairs, 12 mmas with RAW distance 4 ----
#pragma unroll
        for (int kk = 0; kk < 4; kk++) {
            const uint32_t vdb = sb + vb + (kk * 16 + ((lane >> 3) & 1) * 8 + (lane & 7)) * TSTR;
#pragma unroll
            for (int vq = 0; vq < 4; vq++) {
                const int vp0 = 2 * vq, vp1 = 2 * vq + 1;
                uint32_t vH0[4], vL0[4], vH1[4], vL1[4];
                ldsm4t(vH0, vdb + (vp0 * 16 + (lane >> 4) * 8) * 2);
                ldsm4t(vL0, vdb + (vp0 * 16 + (lane >> 4) * 8) * 2 + TILE_H);
                ldsm4t(vH1, vdb + (vp1 * 16 + (lane >> 4) * 8) * 2);
                ldsm4t(vL1, vdb + (vp1 * 16 + (lane >> 4) * 8) * 2 + TILE_H);
                mma16816(o[2 * vp0],     pH[kk], &vH0[0]);
                mma16816(o[2 * vp0 + 1], pH[kk], &vH0[2]);
                mma16816(o[2 * vp1],     pH[kk], &vH1[0]);
                mma16816(o[2 * vp1 + 1], pH[kk], &vH1[2]);
                mma16816(o[2 * vp0],     pH[kk], &vL0[0]);
                mma16816(o[2 * vp0 + 1], pH[kk], &vL0[2]);
                mma16816(o[2 * vp1],     pH[kk], &vL1[0]);
                mma16816(o[2 * vp1 + 1], pH[kk], &vL1[2]);
                mma16816(o[2 * vp0],     pL[kk], &vH0[0]);
                mma16816(o[2 * vp0 + 1], pL[kk], &vH0[2]);
                mma16816(o[2 * vp1],     pL[kk], &vH1[0]);
                mma16816(o[2 * vp1 + 1], pL[kk], &vH1[2]);
            }
        }
    }

    // ---- finalize ----
    lsum0 += __shfl_xor_sync(0xffffffffu, lsum0, 1);
    lsum0 += __shfl_xor_sync(0xffffffffu, lsum0, 2);
    lsum1 += __shfl_xor_sync(0xffffffffu, lsum1, 1);
    lsum1 += __shfl_xor_sync(0xffffffffu, lsum1, 2);
    const float inv0 = 1.0f / lsum0, inv1 = 1.0f / lsum1;

    float* op0 = Out + ((size_t)bh * SQ + qr0) * HD + q2;
    float* op1 = Out + ((size_t)bh * SQ + qr1) * HD + q2;
#pragma unroll
    for (int vp = 0; vp < 8; vp++) {
#pragma unroll
        for (int h = 0; h < 2; h++) {
            const int col = vp * 16 + h * 8;
            float2 w0, w1;
            w0.x = o[2 * vp + h][0] * inv0; w0.y = o[2 * vp + h][1] * inv0;
            w1.x = o[2 * vp + h][2] * inv1; w1.y = o[2 * vp + h][3] * inv1;
            *(float2*)(op0 + col) = w0;
            *(float2*)(op1 + col) = w1;
        }
    }
}

extern "C" void kernel_launch(void* const* d_in, const int* in_sizes, int n_in,
                              void* d_out, int out_size) {
    const float* Q    = (const float*)d_in[0];
    const float* K    = (const float*)d_in[1];
    const float* V    = (const float*)d_in[2];
    const float* Bias = (const float*)d_in[3];
    float* O = (float*)d_out;

    convert_kv<<<8192, 256>>>(K, V);

    cudaFuncSetAttribute(attn_hmma, cudaFuncAttributeMaxDynamicSharedMemorySize, SMEM_TOTAL);
    dim3 grid(SQ / BM, NHD, NB);   // (16,16,2) = 512 CTAs
    attn_hmma<<<grid, NT, SMEM_TOTAL>>>(Q, Bias, O);
}

// round 9
// speedup vs baseline: 1.0189x; 1.0189x over previous
#include <cuda_runtime.h>
#include <cuda_bf16.h>
#include <cstdint>

// Packed-varlen (SEG=1024) causal attention + additive bias, fp32 I/O.
// Round 8: BM=64 / NT=128 / 2 CTAs per SM (cross-CTA latency hiding).
// K double-buffered, V single-buffered (hidden behind QK+softmax).
// bf16 hi/lo 3-product split on mma.sync.m16n8k16; P and Q stay in registers.

#define SQ   2048
#define NB   2
#define NHD  16
#define HD   128
#define SEG  1024
#define BM   64
#define BN   64
#define NT   128
#define ROWSTRIDE (NB*NHD*HD)
#define ATTN_SCALE 0.08838834764831845f

// scratch: per (b,h,s) one 512B row = [hi 128 bf16 | lo 128 bf16]
__device__ __align__(256) static unsigned char KHL[(size_t)NB * NHD * SQ * 512];
__device__ __align__(256) static unsigned char VHL[(size_t)NB * NHD * SQ * 512];

#define TSTR 272
#define TILE_H 17408
#define BUF_SZ 34816
#define SM_K 0                 // K double buffer: 2 x 34816
#define SM_V 69632             // V single buffer: 34816 (Q staging aliases it)
#define SMEM_TOTAL 104448      // 102 KB -> 2 CTAs/SM

__device__ __forceinline__ uint32_t s2u(const void* p) {
    uint32_t a;
    asm("{ .reg .u64 t; cvta.to.shared.u64 t, %1; cvt.u32.u64 %0, t; }" : "=r"(a) : "l"(p));
    return a;
}
__device__ __forceinline__ void split2(float a, float b, uint32_t& hi, uint32_t& lo) {
    __nv_bfloat16 ah = __float2bfloat16_rn(a);
    __nv_bfloat16 bh = __float2bfloat16_rn(b);
    __nv_bfloat16 al = __float2bfloat16_rn(a - __bfloat162float(ah));
    __nv_bfloat16 bl = __float2bfloat16_rn(b - __bfloat162float(bh));
    hi = ((uint32_t)__bfloat16_as_ushort(bh) << 16) | __bfloat16_as_ushort(ah);
    lo = ((uint32_t)__bfloat16_as_ushort(bl) << 16) | __bfloat16_as_ushort(al);
}
__device__ __forceinline__ void ldsm4(uint32_t* r, uint32_t a) {
    asm volatile("ldmatrix.sync.aligned.m8n8.x4.shared.b16 {%0,%1,%2,%3}, [%4];"
                 : "=r"(r[0]), "=r"(r[1]), "=r"(r[2]), "=r"(r[3]) : "r"(a));
}
__device__ __forceinline__ void ldsm4t(uint32_t* r, uint32_t a) {
    asm volatile("ldmatrix.sync.aligned.m8n8.x4.trans.shared.b16 {%0,%1,%2,%3}, [%4];"
                 : "=r"(r[0]), "=r"(r[1]), "=r"(r[2]), "=r"(r[3]) : "r"(a));
}
__device__ __forceinline__ void mma16816(float* c, const uint32_t* a, const uint32_t* b) {
    asm volatile("mma.sync.aligned.m16n8k16.row.col.f32.bf16.bf16.f32 "
                 "{%0,%1,%2,%3}, {%4,%5,%6,%7}, {%8,%9}, {%0,%1,%2,%3};"
                 : "+f"(c[0]), "+f"(c[1]), "+f"(c[2]), "+f"(c[3])
                 : "r"(a[0]), "r"(a[1]), "r"(a[2]), "r"(a[3]), "r"(b[0]), "r"(b[1]));
}
#define CPASYNC16(s, g) asm volatile("cp.async.cg.shared.global [%0], [%1], 16;" :: "r"(s), "l"(g))
#define CPCOMMIT()      asm volatile("cp.async.commit_group;" ::: "memory")
#define CPWAIT0()       asm volatile("cp.async.wait_group 0;" ::: "memory")
#define CPWAIT1()       asm volatile("cp.async.wait_group 1;" ::: "memory")

// ---- pre-pass: K,V fp32 -> bf16 hi/lo rows in scratch ----
__global__ __launch_bounds__(256)
void convert_kv(const float* __restrict__ Kg, const float* __restrict__ Vg) {
    const int idx = blockIdx.x * 256 + threadIdx.x;
    const int row = idx >> 5, f4 = idx & 31;
    const int bh = row >> 11, s = row & 2047;
    const size_t src = (size_t)s * ROWSTRIDE + bh * HD + f4 * 4;
    const size_t dst = (size_t)row * 512 + f4 * 8;
    float4 k = *(const float4*)(Kg + src);
    float4 v = *(const float4*)(Vg + src);
    uint32_t h0, l0, h1, l1;
    split2(k.x, k.y, h0, l0); split2(k.z, k.w, h1, l1);
    *(uint2*)(KHL + dst)       = make_uint2(h0, h1);
    *(uint2*)(KHL + dst + 256) = make_uint2(l0, l1);
    split2(v.x, v.y, h0, l0); split2(v.z, v.w, h1, l1);
    *(uint2*)(VHL + dst)       = make_uint2(h0, h1);
    *(uint2*)(VHL + dst + 256) = make_uint2(l0, l1);
}

// cp.async one 64-row tile (hi+lo) from scratch into an smem buffer.
__device__ __forceinline__ void issue_tile(const unsigned char* scratch, uint32_t sb,
                                           uint32_t smbase, int bh, int g0, int tid) {
#pragma unroll
    for (int i = 0; i < 16; i++) {
        const int c = tid + NT * i, row = c >> 5, f4 = c & 31;
        const unsigned char* src = scratch + (((size_t)(bh * SQ + g0 + row)) << 9) + f4 * 16;
        const uint32_t dst = (f4 < 16) ? (sb + smbase + row * TSTR + f4 * 16)
                                       : (sb + smbase + TILE_H + row * TSTR + (f4 - 16) * 16);
        CPASYNC16(dst, src);
    }
}

__global__ __launch_bounds__(NT, 2)
void attn_hmma(const float* __restrict__ Qg, const float* __restrict__ Bias,
               float* __restrict__ Out) {
    extern __shared__ char smem[];
    const uint32_t sb = s2u(smem);
    const int tid = threadIdx.x, lane = tid & 31, warp = tid >> 5;
    const int m0 = warp * 16;                 // warp's 16 q-rows within BM=64
    const int tile = 31 - (int)blockIdx.x;    // heavy (late-in-segment) tiles first
    const int head = blockIdx.y, batch = blockIdx.z;
    const int q0 = tile * BM, seg0 = (q0 / SEG) * SEG;
    const int bh = batch * NHD + head;
    const int base = bh * HD;
    const int nkt = (q0 - seg0) / BN + 1;

    // ---- prologue: K0 cp.async; Q -> staging (aliases V buf) -> reg frags ----
    issue_tile(KHL, sb, SM_K, bh, seg0, tid);
    CPCOMMIT();
#pragma unroll
    for (int i = 0; i < 16; i++) {
        const int idx = tid + NT * i, row = idx >> 5, f4 = idx & 31;
        const float4 v = *(const float4*)(Qg + (size_t)(q0 + row) * ROWSTRIDE + base + f4 * 4);
        uint32_t h0, l0, h1, l1;
        split2(v.x, v.y, h0, l0); split2(v.z, v.w, h1, l1);
        *(uint2*)(smem + SM_V + row * TSTR + f4 * 8)          = make_uint2(h0, h1);
        *(uint2*)(smem + SM_V + TILE_H + row * TSTR + f4 * 8) = make_uint2(l0, l1);
    }
    __syncthreads();
    uint32_t qH[8][4], qL[8][4];              // persistent Q fragments (64 regs)
#pragma unroll
    for (int ks = 0; ks < 8; ks++) {
        const uint32_t ad = sb + SM_V + (m0 + (lane & 15)) * TSTR
                          + ks * 32 + (lane >> 4) * 16;
        ldsm4(qH[ks], ad);
        ldsm4(qL[ks], ad + TILE_H);
    }

    float o[16][4];
#pragma unroll
    for (int j = 0; j < 16; j++)
#pragma unroll
        for (int r = 0; r < 4; r++) o[j][r] = 0.f;
    float lsum0 = 0.f, lsum1 = 0.f;

    const int r0 = lane >> 2, q2 = (lane & 3) * 2;
    const int qr0 = q0 + m0 + r0, qr1 = qr0 + 8;
    const float* bp0 = Bias + (size_t)batch * SQ * SQ + (size_t)qr0 * SQ;
    const float* bp1 = Bias + (size_t)batch * SQ * SQ + (size_t)qr1 * SQ;

    for (int kt = 0; kt < nkt; kt++) {
        const int k0 = seg0 + kt * BN;
        const uint32_t kb = SM_K + (kt & 1) * BUF_SZ;
        const bool more = (kt + 1 < nkt);

        CPWAIT0();           // K(kt) resident
        __syncthreads();     // all warps past prior PV / Q-frag reads: V buf free

        issue_tile(VHL, sb, SM_V, bh, k0, tid);           // V(kt), hidden by QK
        CPCOMMIT();
        if (more) {
            issue_tile(KHL, sb, SM_K + ((kt + 1) & 1) * BUF_SZ, bh, k0 + BN, tid);
            CPCOMMIT();
        }

        // ---- S = Q K^T : 3 phases x 8 independent accumulators ----
        float c[8][4];
#pragma unroll
        for (int f = 0; f < 8; f++)
#pragma unroll
            for (int r = 0; r < 4; r++) c[f][r] = 0.f;

#pragma unroll
        for (int ks = 0; ks < 8; ks++) {
            uint32_t bH[4][4], bL[4][4];
#pragma unroll
            for (int g = 0; g < 4; g++) {
                const uint32_t bd = sb + kb + (g * 16 + ((lane >> 4) & 1) * 8 + (lane & 7)) * TSTR
                                  + ks * 32 + ((lane >> 3) & 1) * 16;
                ldsm4(bH[g], bd);
                ldsm4(bL[g], bd + TILE_H);
            }
#pragma unroll
            for (int g = 0; g < 4; g++) {
                mma16816(c[2 * g],     qH[ks], &bH[g][0]);
                mma16816(c[2 * g + 1], qH[ks], &bH[g][2]);
            }
#pragma unroll
            for (int g = 0; g < 4; g++) {
                mma16816(c[2 * g],     qH[ks], &bL[g][0]);
                mma16816(c[2 * g + 1], qH[ks], &bL[g][2]);
            }
#pragma unroll
            for (int g = 0; g < 4; g++) {
                mma16816(c[2 * g],     qL[ks], &bH[g][0]);
                mma16816(c[2 * g + 1], qL[ks], &bH[g][2]);
            }
        }

        // ---- softmax (no max-sub; scores O(6)) + causal + bias ----
#pragma unroll
        for (int f = 0; f < 8; f++) {
            const int col = k0 + f * 8 + q2;
            const float2 b0 = __ldg((const float2*)(bp0 + col));
            const float2 b1 = __ldg((const float2*)(bp1 + col));
            const float p0 = (col     <= qr0) ? __expf(c[f][0] * ATTN_SCALE + b0.x) : 0.f;
            const float p1 = (col + 1 <= qr0) ? __expf(c[f][1] * ATTN_SCALE + b0.y) : 0.f;
            const float p2 = (col     <= qr1) ? __expf(c[f][2] * ATTN_SCALE + b1.x) : 0.f;
            const float p3 = (col + 1 <= qr1) ? __expf(c[f][3] * ATTN_SCALE + b1.y) : 0.f;
            lsum0 += p0 + p1;
            lsum1 += p2 + p3;
            c[f][0] = p0; c[f][1] = p1; c[f][2] = p2; c[f][3] = p3;
        }
        uint32_t pH[4][4], pL[4][4];
#pragma unroll
        for (int t = 0; t < 4; t++) {
            split2(c[2 * t][0],     c[2 * t][1],     pH[t][0], pL[t][0]);
            split2(c[2 * t][2],     c[2 * t][3],     pH[t][1], pL[t][1]);
            split2(c[2 * t + 1][0], c[2 * t + 1][1], pH[t][2], pL[t][2]);
            split2(c[2 * t + 1][2], c[2 * t + 1][3], pH[t][3], pL[t][3]);
        }

        if (more) { CPWAIT1(); } else { CPWAIT0(); }   // V(kt) resident
        __syncthreads();                               // V visible to all warps

        // ---- O += P V : V columns in pairs, RAW distance 4 ----
#pragma unroll
        for (int kk = 0; kk < 4; kk++) {
            const uint32_t vdb = sb + SM_V + (kk * 16 + ((lane >> 3) & 1) * 8 + (lane & 7)) * TSTR;
#pragma unroll
            for (int vq = 0; vq < 4; vq++) {
                const int vp0 = 2 * vq, vp1 = 2 * vq + 1;
                uint32_t vH0[4], vL0[4], vH1[4], vL1[4];
                ldsm4t(vH0, vdb + (vp0 * 16 + (lane >> 4) * 8) * 2);
                ldsm4t(vL0, vdb + (vp0 * 16 + (lane >> 4) * 8) * 2 + TILE_H);
                ldsm4t(vH1, vdb + (vp1 * 16 + (lane >> 4) * 8) * 2);
                ldsm4t(vL1, vdb + (vp1 * 16 + (lane >> 4) * 8) * 2 + TILE_H);
                mma16816(o[2 * vp0],     pH[kk], &vH0[0]);
                mma16816(o[2 * vp0 + 1], pH[kk], &vH0[2]);
                mma16816(o[2 * vp1],     pH[kk], &vH1[0]);
                mma16816(o[2 * vp1 + 1], pH[kk], &vH1[2]);
                mma16816(o[2 * vp0],     pH[kk], &vL0[0]);
                mma16816(o[2 * vp0 + 1], pH[kk], &vL0[2]);
                mma16816(o[2 * vp1],     pH[kk], &vL1[0]);
                mma16816(o[2 * vp1 + 1], pH[kk], &vL1[2]);
                mma16816(o[2 * vp0],     pL[kk], &vH0[0]);
                mma16816(o[2 * vp0 + 1], pL[kk], &vH0[2]);
                mma16816(o[2 * vp1],     pL[kk], &vH1[0]);
                mma16816(o[2 * vp1 + 1], pL[kk], &vH1[2]);
            }
        }
    }

    // ---- finalize: row sums warp-local ----
    lsum0 += __shfl_xor_sync(0xffffffffu, lsum0, 1);
    lsum0 += __shfl_xor_sync(0xffffffffu, lsum0, 2);
    lsum1 += __shfl_xor_sync(0xffffffffu, lsum1, 1);
    lsum1 += __shfl_xor_sync(0xffffffffu, lsum1, 2);
    const float inv0 = 1.0f / lsum0, inv1 = 1.0f / lsum1;

    float* op0 = Out + ((size_t)bh * SQ + qr0) * HD + q2;
    float* op1 = Out + ((size_t)bh * SQ + qr1) * HD + q2;
#pragma unroll
    for (int vp = 0; vp < 8; vp++) {
#pragma unroll
        for (int h = 0; h < 2; h++) {
            const int col = vp * 16 + h * 8;
            float2 w0, w1;
            w0.x = o[2 * vp + h][0] * inv0; w0.y = o[2 * vp + h][1] * inv0;
            w1.x = o[2 * vp + h][2] * inv1; w1.y = o[2 * vp + h][3] * inv1;
            *(float2*)(op0 + col) = w0;
            *(float2*)(op1 + col) = w1;
        }
    }
}

extern "C" void kernel_launch(void* const* d_in, const int* in_sizes, int n_in,
                              void* d_out, int out_size) {
    const float* Q    = (const float*)d_in[0];
    const float* K    = (const float*)d_in[1];
    const float* V    = (const float*)d_in[2];
    const float* Bias = (const float*)d_in[3];
    float* O = (float*)d_out;

    convert_kv<<<8192, 256>>>(K, V);

    cudaFuncSetAttribute(attn_hmma, cudaFuncAttributeMaxDynamicSharedMemorySize, SMEM_TOTAL);
    dim3 grid(SQ / BM, NHD, NB);   // (32,16,2) = 1024 CTAs
    attn_hmma<<<grid, NT, SMEM_TOTAL>>>(Q, Bias, O);
}

// round 11
// speedup vs baseline: 1.0952x; 1.0748x over previous
#include <cuda_runtime.h>
#include <cuda_fp16.h>
#include <cstdint>

// Packed-varlen (SEG=1024) causal attention + additive bias, fp32 I/O.
// Round 9: fp16 arithmetic. QK = 3-product fp16 hi/lo split (err ~2^-22).
// PV = 2 products: p rounded ONCE to fp16 and used consistently in numerator
// and denominator (consistent-weight perturbation ~2^-11 -> out err ~2e-4);
// V fp16 hi/lo. BM=64, NT=128, 2 CTAs/SM, K dbuf + V sbuf cp.async.

#define SQ   2048
#define NB   2
#define NHD  16
#define HD   128
#define SEG  1024
#define BM   64
#define BN   64
#define NT   128
#define ROWSTRIDE (NB*NHD*HD)
#define ATTN_SCALE 0.08838834764831845f

// scratch: per (b,h,s) one 512B row = [hi 128 fp16 | lo 128 fp16]
__device__ __align__(256) static unsigned char KHL[(size_t)NB * NHD * SQ * 512];
__device__ __align__(256) static unsigned char VHL[(size_t)NB * NHD * SQ * 512];

#define TSTR 272
#define TILE_H 17408
#define BUF_SZ 34816
#define SM_K 0                 // K double buffer: 2 x 34816
#define SM_V 69632             // V single buffer (Q staging aliases it)
#define SMEM_TOTAL 104448      // 102 KB -> 2 CTAs/SM

__device__ __forceinline__ uint32_t s2u(const void* p) {
    uint32_t a;
    asm("{ .reg .u64 t; cvta.to.shared.u64 t, %1; cvt.u32.u64 %0, t; }" : "=r"(a) : "l"(p));
    return a;
}
__device__ __forceinline__ void split2h(float a, float b, uint32_t& hi, uint32_t& lo) {
    __half ah = __float2half_rn(a);
    __half bh = __float2half_rn(b);
    __half al = __float2half_rn(a - __half2float(ah));
    __half bl = __float2half_rn(b - __half2float(bh));
    hi = ((uint32_t)__half_as_ushort(bh) << 16) | __half_as_ushort(ah);
    lo = ((uint32_t)__half_as_ushort(bl) << 16) | __half_as_ushort(al);
}
__device__ __forceinline__ void ldsm4(uint32_t* r, uint32_t a) {
    asm volatile("ldmatrix.sync.aligned.m8n8.x4.shared.b16 {%0,%1,%2,%3}, [%4];"
                 : "=r"(r[0]), "=r"(r[1]), "=r"(r[2]), "=r"(r[3]) : "r"(a));
}
__device__ __forceinline__ void ldsm4t(uint32_t* r, uint32_t a) {
    asm volatile("ldmatrix.sync.aligned.m8n8.x4.trans.shared.b16 {%0,%1,%2,%3}, [%4];"
                 : "=r"(r[0]), "=r"(r[1]), "=r"(r[2]), "=r"(r[3]) : "r"(a));
}
__device__ __forceinline__ void mma16816(float* c, const uint32_t* a, const uint32_t* b) {
    asm volatile("mma.sync.aligned.m16n8k16.row.col.f32.f16.f16.f32 "
                 "{%0,%1,%2,%3}, {%4,%5,%6,%7}, {%8,%9}, {%0,%1,%2,%3};"
                 : "+f"(c[0]), "+f"(c[1]), "+f"(c[2]), "+f"(c[3])
                 : "r"(a[0]), "r"(a[1]), "r"(a[2]), "r"(a[3]), "r"(b[0]), "r"(b[1]));
}
#define CPASYNC16(s, g) asm volatile("cp.async.cg.shared.global [%0], [%1], 16;" :: "r"(s), "l"(g))
#define CPCOMMIT()      asm volatile("cp.async.commit_group;" ::: "memory")
#define CPWAIT0()       asm volatile("cp.async.wait_group 0;" ::: "memory")
#define CPWAIT1()       asm volatile("cp.async.wait_group 1;" ::: "memory")

// ---- pre-pass: K,V fp32 -> fp16 hi/lo rows in scratch ----
__global__ __launch_bounds__(256)
void convert_kv(const float* __restrict__ Kg, const float* __restrict__ Vg) {
    const int idx = blockIdx.x * 256 + threadIdx.x;
    const int row = idx >> 5, f4 = idx & 31;
    const int bh = row >> 11, s = row & 2047;
    const size_t src = (size_t)s * ROWSTRIDE + bh * HD + f4 * 4;
    const size_t dst = (size_t)row * 512 + f4 * 8;
    float4 k = *(const float4*)(Kg + src);
    float4 v = *(const float4*)(Vg + src);
    uint32_t h0, l0, h1, l1;
    split2h(k.x, k.y, h0, l0); split2h(k.z, k.w, h1, l1);
    *(uint2*)(KHL + dst)       = make_uint2(h0, h1);
    *(uint2*)(KHL + dst + 256) = make_uint2(l0, l1);
    split2h(v.x, v.y, h0, l0); split2h(v.z, v.w, h1, l1);
    *(uint2*)(VHL + dst)       = make_uint2(h0, h1);
    *(uint2*)(VHL + dst + 256) = make_uint2(l0, l1);
}

// cp.async one 64-row tile (hi+lo) from scratch into an smem buffer.
__device__ __forceinline__ void issue_tile(const unsigned char* scratch, uint32_t sb,
                                           uint32_t smbase, int bh, int g0, int tid) {
#pragma unroll
    for (int i = 0; i < 16; i++) {
        const int c = tid + NT * i, row = c >> 5, f4 = c & 31;
        const unsigned char* src = scratch + (((size_t)(bh * SQ + g0 + row)) << 9) + f4 * 16;
        const uint32_t dst = (f4 < 16) ? (sb + smbase + row * TSTR + f4 * 16)
                                       : (sb + smbase + TILE_H + row * TSTR + (f4 - 16) * 16);
        CPASYNC16(dst, src);
    }
}

__global__ __launch_bounds__(NT, 2)
void attn_hmma(const float* __restrict__ Qg, const float* __restrict__ Bias,
               float* __restrict__ Out) {
    extern __shared__ char smem[];
    const uint32_t sb = s2u(smem);
    const int tid = threadIdx.x, lane = tid & 31, warp = tid >> 5;
    const int m0 = warp * 16;
    const int tile = 31 - (int)blockIdx.x;    // heavy tiles first
    const int head = blockIdx.y, batch = blockIdx.z;
    const int q0 = tile * BM, seg0 = (q0 / SEG) * SEG;
    const int bh = batch * NHD + head;
    const int base = bh * HD;
    const int nkt = (q0 - seg0) / BN + 1;

    // ---- prologue: K0 cp.async; Q -> staging (aliases V buf) -> reg frags ----
    issue_tile(KHL, sb, SM_K, bh, seg0, tid);
    CPCOMMIT();
#pragma unroll
    for (int i = 0; i < 16; i++) {
        const int idx = tid + NT * i, row = idx >> 5, f4 = idx & 31;
        const float4 v = *(const float4*)(Qg + (size_t)(q0 + row) * ROWSTRIDE + base + f4 * 4);
        uint32_t h0, l0, h1, l1;
        split2h(v.x, v.y, h0, l0); split2h(v.z, v.w, h1, l1);
        *(uint2*)(smem + SM_V + row * TSTR + f4 * 8)          = make_uint2(h0, h1);
        *(uint2*)(smem + SM_V + TILE_H + row * TSTR + f4 * 8) = make_uint2(l0, l1);
    }
    __syncthreads();
    uint32_t qH[8][4], qL[8][4];              // persistent Q fragments
#pragma unroll
    for (int ks = 0; ks < 8; ks++) {
        const uint32_t ad = sb + SM_V + (m0 + (lane & 15)) * TSTR
                          + ks * 32 + (lane >> 4) * 16;
        ldsm4(qH[ks], ad);
        ldsm4(qL[ks], ad + TILE_H);
    }

    float o[16][4];
#pragma unroll
    for (int j = 0; j < 16; j++)
#pragma unroll
        for (int r = 0; r < 4; r++) o[j][r] = 0.f;
    float lsum0 = 0.f, lsum1 = 0.f;

    const int r0 = lane >> 2, q2 = (lane & 3) * 2;
    const int qr0 = q0 + m0 + r0, qr1 = qr0 + 8;
    const float* bp0 = Bias + (size_t)batch * SQ * SQ + (size_t)qr0 * SQ;
    const float* bp1 = Bias + (size_t)batch * SQ * SQ + (size_t)qr1 * SQ;

    for (int kt = 0; kt < nkt; kt++) {
        const int k0 = seg0 + kt * BN;
        const uint32_t kb = SM_K + (kt & 1) * BUF_SZ;
        const bool more = (kt + 1 < nkt);

        CPWAIT0();           // K(kt) resident
        __syncthreads();     // all warps past prior PV / Q-frag reads: V buf free

        issue_tile(VHL, sb, SM_V, bh, k0, tid);           // V(kt), hidden by QK
        CPCOMMIT();
        if (more) {
            issue_tile(KHL, sb, SM_K + ((kt + 1) & 1) * BUF_SZ, bh, k0 + BN, tid);
            CPCOMMIT();
        }

        // ---- S = Q K^T : fp16 3-product, 3 phases x 8 independent accs ----
        float c[8][4];
#pragma unroll
        for (int f = 0; f < 8; f++)
#pragma unroll
            for (int r = 0; r < 4; r++) c[f][r] = 0.f;

#pragma unroll
        for (int ks = 0; ks < 8; ks++) {
            uint32_t bH[4][4], bL[4][4];
#pragma unroll
            for (int g = 0; g < 4; g++) {
                const uint32_t bd = sb + kb + (g * 16 + ((lane >> 4) & 1) * 8 + (lane & 7)) * TSTR
                                  + ks * 32 + ((lane >> 3) & 1) * 16;
                ldsm4(bH[g], bd);
                ldsm4(bL[g], bd + TILE_H);
            }
#pragma unroll
            for (int g = 0; g < 4; g++) {
                mma16816(c[2 * g],     qH[ks], &bH[g][0]);
                mma16816(c[2 * g + 1], qH[ks], &bH[g][2]);
            }
#pragma unroll
            for (int g = 0; g < 4; g++) {
                mma16816(c[2 * g],     qH[ks], &bL[g][0]);
                mma16816(c[2 * g + 1], qH[ks], &bL[g][2]);
            }
#pragma unroll
            for (int g = 0; g < 4; g++) {
                mma16816(c[2 * g],     qL[ks], &bH[g][0]);
                mma16816(c[2 * g + 1], qL[ks], &bH[g][2]);
            }
        }

        // ---- softmax + causal + bias; p rounded ONCE to fp16 (consistent) ----
        uint32_t pF[4][4];
#pragma unroll
        for (int f = 0; f < 8; f++) {
            const int col = k0 + f * 8 + q2;
            const float2 b0 = __ldg((const float2*)(bp0 + col));
            const float2 b1 = __ldg((const float2*)(bp1 + col));
            const float p0 = (col     <= qr0) ? __expf(c[f][0] * ATTN_SCALE + b0.x) : 0.f;
            const float p1 = (col + 1 <= qr0) ? __expf(c[f][1] * ATTN_SCALE + b0.y) : 0.f;
            const float p2 = (col     <= qr1) ? __expf(c[f][2] * ATTN_SCALE + b1.x) : 0.f;
            const float p3 = (col + 1 <= qr1) ? __expf(c[f][3] * ATTN_SCALE + b1.y) : 0.f;
            const __half h0 = __float2half_rn(p0), h1 = __float2half_rn(p1);
            const __half h2 = __float2half_rn(p2), h3 = __float2half_rn(p3);
            // denominator uses the SAME rounded weights as the PV numerator
            lsum0 += __half2float(h0) + __half2float(h1);
            lsum1 += __half2float(h2) + __half2float(h3);
            const int t = f >> 1, half = f & 1;   // frag kk = t, regs {0,1} or {2,3}
            pF[t][2 * half + 0] = ((uint32_t)__half_as_ushort(h1) << 16) | __half_as_ushort(h0);
            pF[t][2 * half + 1] = ((uint32_t)__half_as_ushort(h3) << 16) | __half_as_ushort(h2);
        }

        if (more) { CPWAIT1(); } else { CPWAIT0(); }   // V(kt) resident
        __syncthreads();                               // V visible to all warps

        // ---- O += p~ V : 2 products (Vhi, Vlo), V columns in pairs ----
#pragma unroll
        for (int kk = 0; kk < 4; kk++) {
            const uint32_t vdb = sb + SM_V + (kk * 16 + ((lane >> 3) & 1) * 8 + (lane & 7)) * TSTR;
#pragma unroll
            for (int vq = 0; vq < 4; vq++) {
                const int vp0 = 2 * vq, vp1 = 2 * vq + 1;
                uint32_t vH0[4], vL0[4], vH1[4], vL1[4];
                ldsm4t(vH0, vdb + (vp0 * 16 + (lane >> 4) * 8) * 2);
                ldsm4t(vL0, vdb + (vp0 * 16 + (lane >> 4) * 8) * 2 + TILE_H);
                ldsm4t(vH1, vdb + (vp1 * 16 + (lane >> 4) * 8) * 2);
                ldsm4t(vL1, vdb + (vp1 * 16 + (lane >> 4) * 8) * 2 + TILE_H);
                mma16816(o[2 * vp0],     pF[kk], &vH0[0]);
                mma16816(o[2 * vp0 + 1], pF[kk], &vH0[2]);
                mma16816(o[2 * vp1],     pF[kk], &vH1[0]);
                mma16816(o[2 * vp1 + 1], pF[kk], &vH1[2]);
                mma16816(o[2 * vp0],     pF[kk], &vL0[0]);
                mma16816(o[2 * vp0 + 1], pF[kk], &vL0[2]);
                mma16816(o[2 * vp1],     pF[kk], &vL1[0]);
                mma16816(o[2 * vp1 + 1], pF[kk], &vL1[2]);
            }
        }
    }

    // ---- finalize: row sums warp-local ----
    lsum0 += __shfl_xor_sync(0xffffffffu, lsum0, 1);
    lsum0 += __shfl_xor_sync(0xffffffffu, lsum0, 2);
    lsum1 += __shfl_xor_sync(0xffffffffu, lsum1, 1);
    lsum1 += __shfl_xor_sync(0xffffffffu, lsum1, 2);
    const float inv0 = 1.0f / lsum0, inv1 = 1.0f / lsum1;

    float* op0 = Out + ((size_t)bh * SQ + qr0) * HD + q2;
    float* op1 = Out + ((size_t)bh * SQ + qr1) * HD + q2;
#pragma unroll
    for (int vp = 0; vp < 8; vp++) {
#pragma unroll
        for (int h = 0; h < 2; h++) {
            const int col = vp * 16 + h * 8;
            float2 w0, w1;
            w0.x = o[2 * vp + h][0] * inv0; w0.y = o[2 * vp + h][1] * inv0;
            w1.x = o[2 * vp + h][2] * inv1; w1.y = o[2 * vp + h][3] * inv1;
            *(float2*)(op0 + col) = w0;
            *(float2*)(op1 + col) = w1;
        }
    }
}

extern "C" void kernel_launch(void* const* d_in, const int* in_sizes, int n_in,
                              void* d_out, int out_size) {
    const float* Q    = (const float*)d_in[0];
    const float* K    = (const float*)d_in[1];
    const float* V    = (const float*)d_in[2];
    const float* Bias = (const float*)d_in[3];
    float* O = (float*)d_out;

    convert_kv<<<8192, 256>>>(K, V);

    cudaFuncSetAttribute(attn_hmma, cudaFuncAttributeMaxDynamicSharedMemorySize, SMEM_TOTAL);
    dim3 grid(SQ / BM, NHD, NB);   // (32,16,2) = 1024 CTAs
    attn_hmma<<<grid, NT, SMEM_TOTAL>>>(Q, Bias, O);
}

// round 13
// speedup vs baseline: 1.4038x; 1.2818x over previous
#include <cuda_runtime.h>
#include <cuda_fp16.h>
#include <cstdint>

// Packed-varlen (SEG=1024) causal attention + additive bias, fp32 I/O.
// Round 10: fp16 1-product QK (Qh*Kh; score err std ~3.5e-4 vs scale O(1)),
// PV 2-product with p rounded ONCE to fp16 used consistently in numerator and
// denominator, V fp16 hi/lo. BM=64, NT=128, 2 CTAs/SM, K dbuf + V sbuf.

#define SQ   2048
#define NB   2
#define NHD  16
#define HD   128
#define SEG  1024
#define BM   64
#define BN   64
#define NT   128
#define ROWSTRIDE (NB*NHD*HD)
#define ATTN_SCALE 0.08838834764831845f

// scratch: K hi-only 256B rows; V hi/lo 512B rows
__device__ __align__(256) static unsigned char KH[(size_t)NB * NHD * SQ * 256];
__device__ __align__(256) static unsigned char VHL[(size_t)NB * NHD * SQ * 512];

#define TSTR 272
#define TILE_H 17408
#define SM_K 0                 // K double buffer: 2 x 17408 (hi only)
#define SM_V 34816             // V buffer: hi 17408 + lo 17408 (Q staging aliases)
#define SMEM_TOTAL 69632       // 68 KB -> 2 CTAs/SM (regs bind occupancy anyway)

__device__ __forceinline__ uint32_t s2u(const void* p) {
    uint32_t a;
    asm("{ .reg .u64 t; cvta.to.shared.u64 t, %1; cvt.u32.u64 %0, t; }" : "=r"(a) : "l"(p));
    return a;
}
__device__ __forceinline__ void split2h(float a, float b, uint32_t& hi, uint32_t& lo) {
    __half ah = __float2half_rn(a);
    __half bh = __float2half_rn(b);
    __half al = __float2half_rn(a - __half2float(ah));
    __half bl = __float2half_rn(b - __half2float(bh));
    hi = ((uint32_t)__half_as_ushort(bh) << 16) | __half_as_ushort(ah);
    lo = ((uint32_t)__half_as_ushort(bl) << 16) | __half_as_ushort(al);
}
__device__ __forceinline__ uint32_t pack2h(float a, float b) {
    __half ah = __float2half_rn(a);
    __half bh = __float2half_rn(b);
    return ((uint32_t)__half_as_ushort(bh) << 16) | __half_as_ushort(ah);
}
__device__ __forceinline__ void ldsm4(uint32_t* r, uint32_t a) {
    asm volatile("ldmatrix.sync.aligned.m8n8.x4.shared.b16 {%0,%1,%2,%3}, [%4];"
                 : "=r"(r[0]), "=r"(r[1]), "=r"(r[2]), "=r"(r[3]) : "r"(a));
}
__device__ __forceinline__ void ldsm4t(uint32_t* r, uint32_t a) {
    asm volatile("ldmatrix.sync.aligned.m8n8.x4.trans.shared.b16 {%0,%1,%2,%3}, [%4];"
                 : "=r"(r[0]), "=r"(r[1]), "=r"(r[2]), "=r"(r[3]) : "r"(a));
}
__device__ __forceinline__ void mma16816(float* c, const uint32_t* a, const uint32_t* b) {
    asm volatile("mma.sync.aligned.m16n8k16.row.col.f32.f16.f16.f32 "
                 "{%0,%1,%2,%3}, {%4,%5,%6,%7}, {%8,%9}, {%0,%1,%2,%3};"
                 : "+f"(c[0]), "+f"(c[1]), "+f"(c[2]), "+f"(c[3])
                 : "r"(a[0]), "r"(a[1]), "r"(a[2]), "r"(a[3]), "r"(b[0]), "r"(b[1]));
}
#define CPASYNC16(s, g) asm volatile("cp.async.cg.shared.global [%0], [%1], 16;" :: "r"(s), "l"(g))
#define CPCOMMIT()      asm volatile("cp.async.commit_group;" ::: "memory")
#define CPWAIT0()       asm volatile("cp.async.wait_group 0;" ::: "memory")
#define CPWAIT1()       asm volatile("cp.async.wait_group 1;" ::: "memory")

// ---- pre-pass: K -> fp16 hi; V -> fp16 hi/lo ----
__global__ __launch_bounds__(256)
void convert_kv(const float* __restrict__ Kg, const float* __restrict__ Vg) {
    const int idx = blockIdx.x * 256 + threadIdx.x;
    const int row = idx >> 5, f4 = idx & 31;
    const int bh = row >> 11, s = row & 2047;
    const size_t src = (size_t)s * ROWSTRIDE + bh * HD + f4 * 4;
    float4 k = *(const float4*)(Kg + src);
    float4 v = *(const float4*)(Vg + src);
    *(uint2*)(KH + (size_t)row * 256 + f4 * 8) =
        make_uint2(pack2h(k.x, k.y), pack2h(k.z, k.w));
    uint32_t h0, l0, h1, l1;
    split2h(v.x, v.y, h0, l0); split2h(v.z, v.w, h1, l1);
    *(uint2*)(VHL + (size_t)row * 512 + f4 * 8)       = make_uint2(h0, h1);
    *(uint2*)(VHL + (size_t)row * 512 + 256 + f4 * 8) = make_uint2(l0, l1);
}

// cp.async one 64-row K tile (hi only, 256B rows) into smem.
__device__ __forceinline__ void issue_k(uint32_t sb, uint32_t smbase, int bh, int g0, int tid) {
#pragma unroll
    for (int i = 0; i < 8; i++) {
        const int c = tid + NT * i, row = c >> 4, f4 = c & 15;
        CPASYNC16(sb + smbase + row * TSTR + f4 * 16,
                  KH + (((size_t)(bh * SQ + g0 + row)) << 8) + f4 * 16);
    }
}
// cp.async one 64-row V tile (hi+lo, 512B rows) into smem.
__device__ __forceinline__ void issue_v(uint32_t sb, uint32_t smbase, int bh, int g0, int tid) {
#pragma unroll
    for (int i = 0; i < 16; i++) {
        const int c = tid + NT * i, row = c >> 5, f4 = c & 31;
        const unsigned char* src = VHL + (((size_t)(bh * SQ + g0 + row)) << 9) + f4 * 16;
        const uint32_t dst = (f4 < 16) ? (sb + smbase + row * TSTR + f4 * 16)
                                       : (sb + smbase + TILE_H + row * TSTR + (f4 - 16) * 16);
        CPASYNC16(dst, src);
    }
}

__global__ __launch_bounds__(NT, 2)
void attn_hmma(const float* __restrict__ Qg, const float* __restrict__ Bias,
               float* __restrict__ Out) {
    extern __shared__ char smem[];
    const uint32_t sb = s2u(smem);
    const int tid = threadIdx.x, lane = tid & 31, warp = tid >> 5;
    const int m0 = warp * 16;
    const int tile = 31 - (int)blockIdx.x;    // heavy tiles first
    const int head = blockIdx.y, batch = blockIdx.z;
    const int q0 = tile * BM, seg0 = (q0 / SEG) * SEG;
    const int bh = batch * NHD + head;
    const int base = bh * HD;
    const int nkt = (q0 - seg0) / BN + 1;

    // ---- prologue: K0 cp.async; Q (hi only) -> staging (aliases V) -> frags ----
    issue_k(sb, SM_K, bh, seg0, tid);
    CPCOMMIT();
#pragma unroll
    for (int i = 0; i < 16; i++) {
        const int idx = tid + NT * i, row = idx >> 5, f4 = idx & 31;
        const float4 v = *(const float4*)(Qg + (size_t)(q0 + row) * ROWSTRIDE + base + f4 * 4);
        *(uint2*)(smem + SM_V + row * TSTR + f4 * 8) =
            make_uint2(pack2h(v.x, v.y), pack2h(v.z, v.w));
    }
    __syncthreads();
    uint32_t qH[8][4];                         // persistent Q hi fragments
#pragma unroll
    for (int ks = 0; ks < 8; ks++) {
        const uint32_t ad = sb + SM_V + (m0 + (lane & 15)) * TSTR
                          + ks * 32 + (lane >> 4) * 16;
        ldsm4(qH[ks], ad);
    }

    float o[16][4];
#pragma unroll
    for (int j = 0; j < 16; j++)
#pragma unroll
        for (int r = 0; r < 4; r++) o[j][r] = 0.f;
    float lsum0 = 0.f, lsum1 = 0.f;

    const int r0 = lane >> 2, q2 = (lane & 3) * 2;
    const int qr0 = q0 + m0 + r0, qr1 = qr0 + 8;
    const float* bp0 = Bias + (size_t)batch * SQ * SQ + (size_t)qr0 * SQ;
    const float* bp1 = Bias + (size_t)batch * SQ * SQ + (size_t)qr1 * SQ;

    for (int kt = 0; kt < nkt; kt++) {
        const int k0 = seg0 + kt * BN;
        const uint32_t kb = SM_K + (kt & 1) * TILE_H;
        const bool more = (kt + 1 < nkt);

        CPWAIT0();           // K(kt) resident
        __syncthreads();     // all warps past prior PV / Q-frag reads: V buf free

        issue_v(sb, SM_V, bh, k0, tid);       // V(kt), hidden by QK + softmax
        CPCOMMIT();
        if (more) {
            issue_k(sb, SM_K + ((kt + 1) & 1) * TILE_H, bh, k0 + BN, tid);
            CPCOMMIT();
        }

        // ---- S = Qh Kh^T : 1 product, 8 independent accumulators ----
        float c[8][4];
#pragma unroll
        for (int f = 0; f < 8; f++)
#pragma unroll
            for (int r = 0; r < 4; r++) c[f][r] = 0.f;

#pragma unroll
        for (int ks = 0; ks < 8; ks++) {
            uint32_t bH[4][4];
#pragma unroll
            for (int g = 0; g < 4; g++) {
                const uint32_t bd = sb + kb + (g * 16 + ((lane >> 4) & 1) * 8 + (lane & 7)) * TSTR
                                  + ks * 32 + ((lane >> 3) & 1) * 16;
                ldsm4(bH[g], bd);
            }
#pragma unroll
            for (int g = 0; g < 4; g++) {
                mma16816(c[2 * g],     qH[ks], &bH[g][0]);
                mma16816(c[2 * g + 1], qH[ks], &bH[g][2]);
            }
        }

        // ---- softmax + causal + bias; p rounded ONCE to fp16 (consistent) ----
        uint32_t pF[4][4];
#pragma unroll
        for (int f = 0; f < 8; f++) {
            const int col = k0 + f * 8 + q2;
            const float2 b0 = __ldg((const float2*)(bp0 + col));
            const float2 b1 = __ldg((const float2*)(bp1 + col));
            const float p0 = (col     <= qr0) ? __expf(c[f][0] * ATTN_SCALE + b0.x) : 0.f;
            const float p1 = (col + 1 <= qr0) ? __expf(c[f][1] * ATTN_SCALE + b0.y) : 0.f;
            const float p2 = (col     <= qr1) ? __expf(c[f][2] * ATTN_SCALE + b1.x) : 0.f;
            const float p3 = (col + 1 <= qr1) ? __expf(c[f][3] * ATTN_SCALE + b1.y) : 0.f;
            const __half h0 = __float2half_rn(p0), h1 = __float2half_rn(p1);
            const __half h2 = __float2half_rn(p2), h3 = __float2half_rn(p3);
            lsum0 += __half2float(h0) + __half2float(h1);   // same weights as PV
            lsum1 += __half2float(h2) + __half2float(h3);
            const int t = f >> 1, half = f & 1;
            pF[t][2 * half + 0] = ((uint32_t)__half_as_ushort(h1) << 16) | __half_as_ushort(h0);
            pF[t][2 * half + 1] = ((uint32_t)__half_as_ushort(h3) << 16) | __half_as_ushort(h2);
        }

        if (more) { CPWAIT1(); } else { CPWAIT0(); }   // V(kt) resident
        __syncthreads();                               // V visible to all warps

        // ---- O += p~ V : 2 products (Vhi, Vlo), V columns in pairs ----
#pragma unroll
        for (int kk = 0; kk < 4; kk++) {
            const uint32_t vdb = sb + SM_V + (kk * 16 + ((lane >> 3) & 1) * 8 + (lane & 7)) * TSTR;
#pragma unroll
            for (int vq = 0; vq < 4; vq++) {
                const int vp0 = 2 * vq, vp1 = 2 * vq + 1;
                uint32_t vH0[4], vL0[4], vH1[4], vL1[4];
                ldsm4t(vH0, vdb + (vp0 * 16 + (lane >> 4) * 8) * 2);
                ldsm4t(vL0, vdb + (vp0 * 16 + (lane >> 4) * 8) * 2 + TILE_H);
                ldsm4t(vH1, vdb + (vp1 * 16 + (lane >> 4) * 8) * 2);
                ldsm4t(vL1, vdb + (vp1 * 16 + (lane >> 4) * 8) * 2 + TILE_H);
                mma16816(o[2 * vp0],     pF[kk], &vH0[0]);
                mma16816(o[2 * vp0 + 1], pF[kk], &vH0[2]);
                mma16816(o[2 * vp1],     pF[kk], &vH1[0]);
                mma16816(o[2 * vp1 + 1], pF[kk], &vH1[2]);
                mma16816(o[2 * vp0],     pF[kk], &vL0[0]);
                mma16816(o[2 * vp0 + 1], pF[kk], &vL0[2]);
                mma16816(o[2 * vp1],     pF[kk], &vL1[0]);
                mma16816(o[2 * vp1 + 1], pF[kk], &vL1[2]);
            }
        }
    }

    // ---- finalize: row sums warp-local ----
    lsum0 += __shfl_xor_sync(0xffffffffu, lsum0, 1);
    lsum0 += __shfl_xor_sync(0xffffffffu, lsum0, 2);
    lsum1 += __shfl_xor_sync(0xffffffffu, lsum1, 1);
    lsum1 += __shfl_xor_sync(0xffffffffu, lsum1, 2);
    const float inv0 = 1.0f / lsum0, inv1 = 1.0f / lsum1;

    float* op0 = Out + ((size_t)bh * SQ + qr0) * HD + q2;
    float* op1 = Out + ((size_t)bh * SQ + qr1) * HD + q2;
#pragma unroll
    for (int vp = 0; vp < 8; vp++) {
#pragma unroll
        for (int h = 0; h < 2; h++) {
            const int col = vp * 16 + h * 8;
            float2 w0, w1;
            w0.x = o[2 * vp + h][0] * inv0; w0.y = o[2 * vp + h][1] * inv0;
            w1.x = o[2 * vp + h][2] * inv1; w1.y = o[2 * vp + h][3] * inv1;
            *(float2*)(op0 + col) = w0;
            *(float2*)(op1 + col) = w1;
        }
    }
}

extern "C" void kernel_launch(void* const* d_in, const int* in_sizes, int n_in,
                              void* d_out, int out_size) {
    const float* Q    = (const float*)d_in[0];
    const float* K    = (const float*)d_in[1];
    const float* V    = (const float*)d_in[2];
    const float* Bias = (const float*)d_in[3];
    float* O = (float*)d_out;

    convert_kv<<<8192, 256>>>(K, V);

    cudaFuncSetAttribute(attn_hmma, cudaFuncAttributeMaxDynamicSharedMemorySize, SMEM_TOTAL);
    dim3 grid(SQ / BM, NHD, NB);   // (32,16,2) = 1024 CTAs
    attn_hmma<<<grid, NT, SMEM_TOTAL>>>(Q, Bias, O);
}

// round 14
// speedup vs baseline: 1.9863x; 1.4149x over previous
#include <cuda_runtime.h>
#include <cuda_fp16.h>
#include <cstdint>

// Packed-varlen (SEG=1024) causal attention + additive bias, fp32 I/O.
// Round 11: fp16 1-product QK (Qh*Kh) and 1-product PV (p~*Vh) with p rounded
// once to fp16 and used consistently in numerator and denominator.
// K and V both double-buffered cp.async -> ONE wait + ONE barrier per k-tile.

#define SQ   2048
#define NB   2
#define NHD  16
#define HD   128
#define SEG  1024
#define BM   64
#define BN   64
#define NT   128
#define ROWSTRIDE (NB*NHD*HD)
#define ATTN_SCALE 0.08838834764831845f

// scratch: fp16 hi rows, 256B per (b,h,s)
__device__ __align__(256) static unsigned char KH[(size_t)NB * NHD * SQ * 256];
__device__ __align__(256) static unsigned char VH[(size_t)NB * NHD * SQ * 256];

#define TSTR 272
#define TILE_H 17408
#define SM_K 0                 // K double buffer: 2 x 17408
#define SM_V 34816             // V double buffer: 2 x 17408 (Q staging aliases)
#define SM_QSTG 34816          // prologue only: Q hi 128 x 272 = 34816
#define SMEM_TOTAL 69632       // 68 KB -> 2 CTAs/SM

__device__ __forceinline__ uint32_t s2u(const void* p) {
    uint32_t a;
    asm("{ .reg .u64 t; cvta.to.shared.u64 t, %1; cvt.u32.u64 %0, t; }" : "=r"(a) : "l"(p));
    return a;
}
__device__ __forceinline__ uint32_t pack2h(float a, float b) {
    __half ah = __float2half_rn(a);
    __half bh = __float2half_rn(b);
    return ((uint32_t)__half_as_ushort(bh) << 16) | __half_as_ushort(ah);
}
__device__ __forceinline__ void ldsm4(uint32_t* r, uint32_t a) {
    asm volatile("ldmatrix.sync.aligned.m8n8.x4.shared.b16 {%0,%1,%2,%3}, [%4];"
                 : "=r"(r[0]), "=r"(r[1]), "=r"(r[2]), "=r"(r[3]) : "r"(a));
}
__device__ __forceinline__ void ldsm4t(uint32_t* r, uint32_t a) {
    asm volatile("ldmatrix.sync.aligned.m8n8.x4.trans.shared.b16 {%0,%1,%2,%3}, [%4];"
                 : "=r"(r[0]), "=r"(r[1]), "=r"(r[2]), "=r"(r[3]) : "r"(a));
}
__device__ __forceinline__ void mma16816(float* c, const uint32_t* a, const uint32_t* b) {
    asm volatile("mma.sync.aligned.m16n8k16.row.col.f32.f16.f16.f32 "
                 "{%0,%1,%2,%3}, {%4,%5,%6,%7}, {%8,%9}, {%0,%1,%2,%3};"
                 : "+f"(c[0]), "+f"(c[1]), "+f"(c[2]), "+f"(c[3])
                 : "r"(a[0]), "r"(a[1]), "r"(a[2]), "r"(a[3]), "r"(b[0]), "r"(b[1]));
}
#define CPASYNC16(s, g) asm volatile("cp.async.cg.shared.global [%0], [%1], 16;" :: "r"(s), "l"(g))
#define CPCOMMIT()      asm volatile("cp.async.commit_group;" ::: "memory")
#define CPWAIT0()       asm volatile("cp.async.wait_group 0;" ::: "memory")

// ---- pre-pass: K,V fp32 -> fp16 hi rows in scratch ----
__global__ __launch_bounds__(256)
void convert_kv(const float* __restrict__ Kg, const float* __restrict__ Vg) {
    const int idx = blockIdx.x * 256 + threadIdx.x;
    const int row = idx >> 5, f4 = idx & 31;
    const int bh = row >> 11, s = row & 2047;
    const size_t src = (size_t)s * ROWSTRIDE + bh * HD + f4 * 4;
    float4 k = *(const float4*)(Kg + src);
    float4 v = *(const float4*)(Vg + src);
    *(uint2*)(KH + (size_t)row * 256 + f4 * 8) =
        make_uint2(pack2h(k.x, k.y), pack2h(k.z, k.w));
    *(uint2*)(VH + (size_t)row * 256 + f4 * 8) =
        make_uint2(pack2h(v.x, v.y), pack2h(v.z, v.w));
}

// cp.async one 64-row fp16 tile (256B rows) into smem at smbase.
__device__ __forceinline__ void issue_tile(const unsigned char* scratch, uint32_t sb,
                                           uint32_t smbase, int bh, int g0, int tid) {
#pragma unroll
    for (int i = 0; i < 8; i++) {
        const int c = tid + NT * i, row = c >> 4, f4 = c & 15;
        CPASYNC16(sb + smbase + row * TSTR + f4 * 16,
                  scratch + (((size_t)(bh * SQ + g0 + row)) << 8) + f4 * 16);
    }
}

__global__ __launch_bounds__(NT, 2)
void attn_hmma(const float* __restrict__ Qg, const float* __restrict__ Bias,
               float* __restrict__ Out) {
    extern __shared__ char smem[];
    const uint32_t sb = s2u(smem);
    const int tid = threadIdx.x, lane = tid & 31, warp = tid >> 5;
    const int m0 = warp * 16;
    const int tile = 31 - (int)blockIdx.x;    // heavy tiles first
    const int head = blockIdx.y, batch = blockIdx.z;
    const int q0 = tile * BM, seg0 = (q0 / SEG) * SEG;
    const int bh = batch * NHD + head;
    const int base = bh * HD;
    const int nkt = (q0 - seg0) / BN + 1;

    // ---- prologue: K0 cp.async; Q hi -> staging (aliases V bufs) -> frags ----
    issue_tile(KH, sb, SM_K, bh, seg0, tid);
    CPCOMMIT();
#pragma unroll
    for (int i = 0; i < 16; i++) {
        const int idx = tid + NT * i, row = idx >> 5, f4 = idx & 31;
        const float4 v = *(const float4*)(Qg + (size_t)(q0 + row) * ROWSTRIDE + base + f4 * 4);
        *(uint2*)(smem + SM_QSTG + row * TSTR + f4 * 8) =
            make_uint2(pack2h(v.x, v.y), pack2h(v.z, v.w));
    }
    __syncthreads();
    uint32_t qH[8][4];                        // persistent Q hi fragments
#pragma unroll
    for (int ks = 0; ks < 8; ks++) {
        const uint32_t ad = sb + SM_QSTG + (m0 + (lane & 15)) * TSTR
                          + ks * 32 + (lane >> 4) * 16;
        ldsm4(qH[ks], ad);
    }
    __syncthreads();                          // staging free -> V buffers usable
    issue_tile(VH, sb, SM_V, bh, seg0, tid);  // V0 into V buf 0
    CPCOMMIT();

    float o[16][4];
#pragma unroll
    for (int j = 0; j < 16; j++)
#pragma unroll
        for (int r = 0; r < 4; r++) o[j][r] = 0.f;
    float lsum0 = 0.f, lsum1 = 0.f;

    const int r0 = lane >> 2, q2 = (lane & 3) * 2;
    const int qr0 = q0 + m0 + r0, qr1 = qr0 + 8;
    const float* bp0 = Bias + (size_t)batch * SQ * SQ + (size_t)qr0 * SQ;
    const float* bp1 = Bias + (size_t)batch * SQ * SQ + (size_t)qr1 * SQ;

    for (int kt = 0; kt < nkt; kt++) {
        const int k0 = seg0 + kt * BN;
        const uint32_t kb = SM_K + (kt & 1) * TILE_H;
        const uint32_t vb = SM_V + (kt & 1) * TILE_H;

        CPWAIT0();           // K(kt), V(kt) resident
        __syncthreads();     // all warps done reading the other buffers

        if (kt + 1 < nkt) {  // prefetch K(kt+1), V(kt+1) into other buffers
            const uint32_t nb = (kt + 1) & 1;
            issue_tile(KH, sb, SM_K + nb * TILE_H, bh, k0 + BN, tid);
            issue_tile(VH, sb, SM_V + nb * TILE_H, bh, k0 + BN, tid);
            CPCOMMIT();
        }

        // ---- S = Qh Kh^T : 1 product, 8 independent accumulators ----
        float c[8][4];
#pragma unroll
        for (int f = 0; f < 8; f++)
#pragma unroll
            for (int r = 0; r < 4; r++) c[f][r] = 0.f;

#pragma unroll
        for (int ks = 0; ks < 8; ks++) {
            uint32_t bH[4][4];
#pragma unroll
            for (int g = 0; g < 4; g++) {
                const uint32_t bd = sb + kb + (g * 16 + ((lane >> 4) & 1) * 8 + (lane & 7)) * TSTR
                                  + ks * 32 + ((lane >> 3) & 1) * 16;
                ldsm4(bH[g], bd);
            }
#pragma unroll
            for (int g = 0; g < 4; g++) {
                mma16816(c[2 * g],     qH[ks], &bH[g][0]);
                mma16816(c[2 * g + 1], qH[ks], &bH[g][2]);
            }
        }

        // ---- softmax + causal + bias; p rounded ONCE to fp16 (consistent) ----
        uint32_t pF[4][4];
#pragma unroll
        for (int f = 0; f < 8; f++) {
            const int col = k0 + f * 8 + q2;
            const float2 b0 = __ldg((const float2*)(bp0 + col));
            const float2 b1 = __ldg((const float2*)(bp1 + col));
            const float p0 = (col     <= qr0) ? __expf(c[f][0] * ATTN_SCALE + b0.x) : 0.f;
            const float p1 = (col + 1 <= qr0) ? __expf(c[f][1] * ATTN_SCALE + b0.y) : 0.f;
            const float p2 = (col     <= qr1) ? __expf(c[f][2] * ATTN_SCALE + b1.x) : 0.f;
            const float p3 = (col + 1 <= qr1) ? __expf(c[f][3] * ATTN_SCALE + b1.y) : 0.f;
            const __half h0 = __float2half_rn(p0), h1 = __float2half_rn(p1);
            const __half h2 = __float2half_rn(p2), h3 = __float2half_rn(p3);
            lsum0 += __half2float(h0) + __half2float(h1);   // same weights as PV
            lsum1 += __half2float(h2) + __half2float(h3);
            const int t = f >> 1, half = f & 1;
            pF[t][2 * half + 0] = ((uint32_t)__half_as_ushort(h1) << 16) | __half_as_ushort(h0);
            pF[t][2 * half + 1] = ((uint32_t)__half_as_ushort(h3) << 16) | __half_as_ushort(h2);
        }

        // ---- O += p~ Vh : 1 product, V columns in pairs ----
#pragma unroll
        for (int kk = 0; kk < 4; kk++) {
            const uint32_t vdb = sb + vb + (kk * 16 + ((lane >> 3) & 1) * 8 + (lane & 7)) * TSTR;
#pragma unroll
            for (int vq = 0; vq < 4; vq++) {
                const int vp0 = 2 * vq, vp1 = 2 * vq + 1;
                uint32_t vH0[4], vH1[4];
                ldsm4t(vH0, vdb + (vp0 * 16 + (lane >> 4) * 8) * 2);
                ldsm4t(vH1, vdb + (vp1 * 16 + (lane >> 4) * 8) * 2);
                mma16816(o[2 * vp0],     pF[kk], &vH0[0]);
                mma16816(o[2 * vp0 + 1], pF[kk], &vH0[2]);
                mma16816(o[2 * vp1],     pF[kk], &vH1[0]);
                mma16816(o[2 * vp1 + 1], pF[kk], &vH1[2]);
            }
        }
    }

    // ---- finalize: row sums warp-local ----
    lsum0 += __shfl_xor_sync(0xffffffffu, lsum0, 1);
    lsum0 += __shfl_xor_sync(0xffffffffu, lsum0, 2);
    lsum1 += __shfl_xor_sync(0xffffffffu, lsum1, 1);
    lsum1 += __shfl_xor_sync(0xffffffffu, lsum1, 2);
    const float inv0 = 1.0f / lsum0, inv1 = 1.0f / lsum1;

    float* op0 = Out + ((size_t)bh * SQ + qr0) * HD + q2;
    float* op1 = Out + ((size_t)bh * SQ + qr1) * HD + q2;
#pragma unroll
    for (int vp = 0; vp < 8; vp++) {
#pragma unroll
        for (int h = 0; h < 2; h++) {
            const int col = vp * 16 + h * 8;
            float2 w0, w1;
            w0.x = o[2 * vp + h][0] * inv0; w0.y = o[2 * vp + h][1] * inv0;
            w1.x = o[2 * vp + h][2] * inv1; w1.y = o[2 * vp + h][3] * inv1;
            *(float2*)(op0 + col) = w0;
            *(float2*)(op1 + col) = w1;
        }
    }
}

extern "C" void kernel_launch(void* const* d_in, const int* in_sizes, int n_in,
                              void* d_out, int out_size) {
    const float* Q    = (const float*)d_in[0];
    const float* K    = (const float*)d_in[1];
    const float* V    = (const float*)d_in[2];
    const float* Bias = (const float*)d_in[3];
    float* O = (float*)d_out;

    convert_kv<<<8192, 256>>>(K, V);

    cudaFuncSetAttribute(attn_hmma, cudaFuncAttributeMaxDynamicSharedMemorySize, SMEM_TOTAL);
    dim3 grid(SQ / BM, NHD, NB);   // (32,16,2) = 1024 CTAs
    attn_hmma<<<grid, NT, SMEM_TOTAL>>>(Q, Bias, O);
}